// round 14
// baseline (speedup 1.0000x reference)
#include <cuda_runtime.h>
#include <cuda_fp16.h>
#include <cstdint>
#include <math.h>

#define Bn  8
#define Cin 1024
#define Sn  2048
#define KD  512
#define OD  1024
#define QKN 1024   // merged q|k output width

// ---------------- scratch (all single fp16 planes) ---------------------------
__device__ __align__(128) __half g_x16 [(size_t)Bn * Sn * Cin];  // xT fp16 (B,S,C)
__device__ __align__(128) __half g_wqk [(size_t)QKN * Cin];      // [Wq|Wk] fp16
__device__ __align__(128) __half g_wv  [(size_t)OD * Cin];       // Wv fp16
__device__ __align__(128) float  g_bqk[QKN];
__device__ __align__(128) __half g_qk [(size_t)Bn * Sn * QKN];   // q cols 0-511, k 512-1023
__device__ __align__(128) __half g_v  [(size_t)Bn * OD * Sn];    // v fp16 (B,OD,S)
__device__ __align__(128) __half g_e  [(size_t)Bn * Sn * Sn];    // exp(scores) fp16
__device__ __align__(128) float  g_psum[(size_t)Bn * 16 * Sn];
__device__ __align__(128) float  g_inv[(size_t)Bn * Sn];

// ---------------- helpers ----------------------------------------------------
__device__ __forceinline__ uint32_t smem_u32(const void* p) {
    uint32_t a;
    asm("{ .reg .u64 t; cvta.to.shared.u64 t, %1; cvt.u32.u64 %0, t; }" : "=r"(a) : "l"(p));
    return a;
}

#define LDSM_X4(r0, r1, r2, r3, addr) \
    asm volatile("ldmatrix.sync.aligned.m8n8.x4.shared.b16 {%0,%1,%2,%3}, [%4];" \
                 : "=r"(r0), "=r"(r1), "=r"(r2), "=r"(r3) : "r"(addr))

__device__ __forceinline__ void mma16816h(float* d, const uint32_t* a, const uint32_t* b) {
    asm volatile(
        "mma.sync.aligned.m16n8k16.row.col.f32.f16.f16.f32 "
        "{%0,%1,%2,%3}, {%4,%5,%6,%7}, {%8,%9}, {%0,%1,%2,%3};"
        : "+f"(d[0]), "+f"(d[1]), "+f"(d[2]), "+f"(d[3])
        : "r"(a[0]), "r"(a[1]), "r"(a[2]), "r"(a[3]), "r"(b[0]), "r"(b[1]));
}

#define CP_ASYNC16(dst, src) \
    asm volatile("cp.async.cg.shared.global [%0], [%1], 16;" :: "r"(dst), "l"(src) : "memory")
#define CP_COMMIT()  asm volatile("cp.async.commit_group;" ::: "memory")
#define CP_WAIT(n)   asm volatile("cp.async.wait_group %0;" :: "n"(n) : "memory")

// tile: 128 rows x 32 fp16 (64B rows); 16B-chunk swizzle c4 ^= (row>>1)&3
__device__ __forceinline__ void cp_tile(uint32_t sdst, const __half* __restrict__ g,
                                        int ld, int row0, int kc, int tid) {
#pragma unroll
    for (int it = 0; it < 2; it++) {
        int slot = tid + it * 256;
        int row  = slot >> 2;
        int c4   = slot & 3;
        uint32_t off = (uint32_t)row * 64 + (uint32_t)((c4 ^ ((row >> 1) & 3)) << 4);
        CP_ASYNC16(sdst + off, g + (size_t)(row0 + row) * ld + kc * 32 + c4 * 8);
    }
}

#define NSTAGE 3

// ================= 1x1-plane fp16 GEMM, 128x128 tile, 2 CTAs/SM =============
// D[m,n] = alpha * sum_k A[m,k]*B[n,k]
// EPI: 1 = +bias[n], fp16 out             (qk projection)
//      2 = +bias[m], fp16 out             (v projection)
//      3 = exp(d*alpha) -> fp16 out + renormalized psum (scores)
//      4 = d * inv[b*Sn+n], fp32 out      (PV, deferred normalization)
#define S11_STAGE 16384        // A 8K | B 8K
#define S11_SMEM  (NSTAGE * S11_STAGE)

template<int EPI>
__global__ void __launch_bounds__(256, 2)
gemm_s(const __half* __restrict__ A, const __half* __restrict__ B,
       const float* __restrict__ bias, float* __restrict__ aux,
       void* __restrict__ C,
       int lda, int ldb, int ldc, int nK,
       size_t sA, size_t sB, size_t sC, float alpha)
{
    extern __shared__ __align__(1024) char smem[];
    const uint32_t sm = smem_u32(smem);
    const int tid  = threadIdx.x;
    const int lane = tid & 31;
    const int wid  = tid >> 5;
    const int m0   = blockIdx.y * 128;
    const int n0   = blockIdx.x * 128;
    const int mW   = (wid >> 2) * 64;
    const int nW   = (wid & 3) * 32;

    A += (size_t)blockIdx.z * sA;
    B += (size_t)blockIdx.z * sB;

    float acc[4][4][4];
#pragma unroll
    for (int i = 0; i < 4; i++)
#pragma unroll
        for (int j = 0; j < 4; j++) {
            acc[i][j][0] = 0.f; acc[i][j][1] = 0.f; acc[i][j][2] = 0.f; acc[i][j][3] = 0.f;
        }

    const uint32_t rl   = lane & 15;
    const uint32_t khA  = lane >> 4;
    const uint32_t swA  = (rl >> 1) & 3;
    const uint32_t aRow = (uint32_t)(mW + rl) * 64;
    const uint32_t rnl  = ((lane >> 4) << 3) | (lane & 7);
    const uint32_t khB  = (lane >> 3) & 1;
    const uint32_t swB  = (rnl >> 1) & 3;
    const uint32_t bRow = (uint32_t)(nW + rnl) * 64;

#pragma unroll
    for (int p = 0; p < 2; p++) {
        if (p < nK) {
            const uint32_t st = sm + p * S11_STAGE;
            cp_tile(st,        A, lda, m0, p, tid);
            cp_tile(st + 8192, B, ldb, n0, p, tid);
        }
        CP_COMMIT();
    }

    for (int i = 0; i < nK; i++) {
        CP_WAIT(1);
        __syncthreads();

        const uint32_t stg = sm + (uint32_t)(i % NSTAGE) * S11_STAGE;
#pragma unroll
        for (int ks = 0; ks < 2; ks++) {
            const uint32_t aCh = (uint32_t)((ks * 2 + khA) ^ swA) << 4;
            const uint32_t bCh = (uint32_t)((ks * 2 + khB) ^ swB) << 4;
            uint32_t a[4][4], b[8];
#pragma unroll
            for (int mt = 0; mt < 4; mt++) {
                LDSM_X4(a[mt][0], a[mt][1], a[mt][2], a[mt][3],
                        stg + aRow + mt * 1024 + aCh);
            }
            LDSM_X4(b[0], b[1], b[2], b[3], stg + 8192 + bRow + bCh);
            LDSM_X4(b[4], b[5], b[6], b[7], stg + 8192 + bRow + 1024 + bCh);

#pragma unroll
            for (int mt = 0; mt < 4; mt++)
#pragma unroll
                for (int nt = 0; nt < 4; nt++)
                    mma16816h(acc[mt][nt], a[mt], &b[nt * 2]);
        }

        const int nx = i + 2;
        if (nx < nK) {
            const uint32_t st = sm + (uint32_t)(nx % NSTAGE) * S11_STAGE;
            cp_tile(st,        A, lda, m0, nx, tid);
            cp_tile(st + 8192, B, ldb, n0, nx, tid);
        }
        CP_COMMIT();
    }
    __syncthreads();   // smem reusable below

    // ---- epilogue ----
    const int g  = lane >> 2;
    const int tg = lane & 3;
    float rsum[4][2];
    if (EPI == 3) {
#pragma unroll
        for (int mt = 0; mt < 4; mt++) { rsum[mt][0] = 0.f; rsum[mt][1] = 0.f; }
    }

#pragma unroll
    for (int mt = 0; mt < 4; mt++) {
        const int m = m0 + mW + mt * 16 + g;
        float bm0 = 0.f, bm8 = 0.f;
        if (EPI == 2) { bm0 = bias[m]; bm8 = bias[m + 8]; }
#pragma unroll
        for (int nt = 0; nt < 4; nt++) {
            const int n = n0 + nW + nt * 8 + tg * 2;
            float d0 = acc[mt][nt][0] * alpha;
            float d1 = acc[mt][nt][1] * alpha;
            float d2 = acc[mt][nt][2] * alpha;
            float d3 = acc[mt][nt][3] * alpha;
            if (EPI == 1) {
                float2 bb = *(const float2*)(bias + n);
                d0 += bb.x; d1 += bb.y; d2 += bb.x; d3 += bb.y;
            } else if (EPI == 2) {
                d0 += bm0; d1 += bm0; d2 += bm8; d3 += bm8;
            }
            if (EPI == 4) {
                float2 iv = *(const float2*)(aux + (size_t)blockIdx.z * Sn + n);
                float* Cf = (float*)C + (size_t)blockIdx.z * sC;
                float2 o0 = { d0 * iv.x, d1 * iv.y };
                float2 o1 = { d2 * iv.x, d3 * iv.y };
                *(float2*)(Cf + (size_t)m * ldc + n)       = o0;
                *(float2*)(Cf + (size_t)(m + 8) * ldc + n) = o1;
            } else {
                __half e0, e1, e2, e3;
                if (EPI == 3) {
                    e0 = __float2half(__expf(d0));
                    e1 = __float2half(__expf(d1));
                    e2 = __float2half(__expf(d2));
                    e3 = __float2half(__expf(d3));
                    // accumulate ROUNDED values -> normalization exact
                    rsum[mt][0] += __half2float(e0) + __half2float(e1);
                    rsum[mt][1] += __half2float(e2) + __half2float(e3);
                } else {
                    e0 = __float2half(d0); e1 = __float2half(d1);
                    e2 = __float2half(d2); e3 = __float2half(d3);
                }
                __half* Ch = (__half*)C + (size_t)blockIdx.z * sC;
                *(__half2*)(Ch + (size_t)m * ldc + n)       = __halves2half2(e0, e1);
                *(__half2*)(Ch + (size_t)(m + 8) * ldc + n) = __halves2half2(e2, e3);
            }
        }
    }

    if (EPI == 3) {
#pragma unroll
        for (int mt = 0; mt < 4; mt++) {
#pragma unroll
            for (int h = 0; h < 2; h++) {
                float s = rsum[mt][h];
                s += __shfl_xor_sync(0xffffffffu, s, 1);
                s += __shfl_xor_sync(0xffffffffu, s, 2);
                rsum[mt][h] = s;
            }
        }
        float* ss = (float*)smem;
        const int nWj = wid & 3;
        if (tg == 0) {
#pragma unroll
            for (int mt = 0; mt < 4; mt++) {
                ss[nWj * 128 + mW + mt * 16 + g]     = rsum[mt][0];
                ss[nWj * 128 + mW + mt * 16 + 8 + g] = rsum[mt][1];
            }
        }
        __syncthreads();
        if (tid < 128) {
            float t = ss[tid] + ss[128 + tid] + ss[256 + tid] + ss[384 + tid];
            aux[((size_t)blockIdx.z * 16 + blockIdx.x) * Sn + m0 + tid] = t;
        }
    }
}

// ---------------- converters --------------------------------------------------
__global__ void __launch_bounds__(256)
xpose16(const float* __restrict__ x, __half* __restrict__ xT)
{
    __shared__ float t[32][33];
    const int tx = threadIdx.x, ty = threadIdx.y;
    const int s0 = blockIdx.x * 32, c0 = blockIdx.y * 32;
    const size_t bi = (size_t)blockIdx.z * Cin * Sn;
    const size_t bo = (size_t)blockIdx.z * Sn * Cin;
#pragma unroll
    for (int j = ty; j < 32; j += 8)
        t[j][tx] = x[bi + (size_t)(c0 + j) * Sn + s0 + tx];
    __syncthreads();
#pragma unroll
    for (int j = ty; j < 32; j += 8)
        xT[bo + (size_t)(s0 + j) * Cin + c0 + tx] = __float2half(t[tx][j]);
}

__global__ void __launch_bounds__(256)
cvt16(const float* __restrict__ in, __half* __restrict__ o, int n4)
{
    int i = blockIdx.x * 256 + threadIdx.x;
    if (i < n4) {
        float4 v = ((const float4*)in)[i];
        ((__half2*)o)[i * 2]     = __halves2half2(__float2half(v.x), __float2half(v.y));
        ((__half2*)o)[i * 2 + 1] = __halves2half2(__float2half(v.z), __float2half(v.w));
    }
}

__global__ void __launch_bounds__(256)
reduce_inv(const float* __restrict__ psum, float* __restrict__ inv)
{
    int i = blockIdx.x * 256 + threadIdx.x;
    int b = i >> 11, s = i & 2047;
    const float* p = psum + (size_t)b * 16 * Sn + s;
    float t = 0.f;
#pragma unroll
    for (int j = 0; j < 16; j++) t += p[(size_t)j * Sn];
    inv[i] = 1.0f / t;
}

// -----------------------------------------------------------------------------
extern "C" void kernel_launch(void* const* d_in, const int* in_sizes, int n_in,
                              void* d_out, int out_size)
{
    (void)in_sizes; (void)n_in; (void)out_size;
    const float* x  = (const float*)d_in[0];
    const float* wq = (const float*)d_in[1];
    const float* bq = (const float*)d_in[2];
    const float* wk = (const float*)d_in[3];
    const float* bk = (const float*)d_in[4];
    const float* wv = (const float*)d_in[5];
    const float* bv = (const float*)d_in[6];
    float* out = (float*)d_out;

    __half *x16, *wqk, *wv16, *qk16, *v16, *eP;
    float *bqk, *psum, *inv;
    cudaGetSymbolAddress((void**)&x16,  g_x16);
    cudaGetSymbolAddress((void**)&wqk,  g_wqk);
    cudaGetSymbolAddress((void**)&wv16, g_wv);
    cudaGetSymbolAddress((void**)&bqk,  g_bqk);
    cudaGetSymbolAddress((void**)&qk16, g_qk);
    cudaGetSymbolAddress((void**)&v16,  g_v);
    cudaGetSymbolAddress((void**)&eP,   g_e);
    cudaGetSymbolAddress((void**)&psum, g_psum);  cudaGetSymbolAddress((void**)&inv,  g_inv);

    cudaFuncSetAttribute(gemm_s<1>, cudaFuncAttributeMaxDynamicSharedMemorySize, S11_SMEM);
    cudaFuncSetAttribute(gemm_s<2>, cudaFuncAttributeMaxDynamicSharedMemorySize, S11_SMEM);
    cudaFuncSetAttribute(gemm_s<3>, cudaFuncAttributeMaxDynamicSharedMemorySize, S11_SMEM);
    cudaFuncSetAttribute(gemm_s<4>, cudaFuncAttributeMaxDynamicSharedMemorySize, S11_SMEM);

    // ---- conversions ----
    xpose16<<<dim3(Sn / 32, Cin / 32, Bn), dim3(32, 8)>>>(x, x16);
    cvt16<<<(KD * Cin / 4 + 255) / 256, 256>>>(wq, wqk, KD * Cin / 4);
    cvt16<<<(KD * Cin / 4 + 255) / 256, 256>>>(wk, wqk + (size_t)KD * Cin, KD * Cin / 4);
    cvt16<<<(OD * Cin / 4 + 255) / 256, 256>>>(wv, wv16, OD * Cin / 4);
    cudaMemcpyAsync(bqk,      bq, KD * sizeof(float), cudaMemcpyDeviceToDevice, 0);
    cudaMemcpyAsync(bqk + KD, bk, KD * sizeof(float), cudaMemcpyDeviceToDevice, 0);

    const size_t sxT = (size_t)Sn * Cin;
    const size_t sqk = (size_t)Sn * QKN;
    const size_t sv  = (size_t)OD * Sn;
    const size_t ssc = (size_t)Sn * Sn;

    // qk = x16 @ Wqk^T + bias -> (B,S,1024) fp16   [m=s, n=ch, k=c]
    gemm_s<1><<<dim3(QKN / 128, Sn / 128, Bn), 256, S11_SMEM>>>(
        x16, wqk, bqk, nullptr, qk16,
        Cin, Cin, QKN, Cin / 32, sxT, 0, sqk, 1.0f);

    // v = Wv @ x16 + bv -> (B,OD,S) fp16   [m=o, n=s, k=c]
    gemm_s<2><<<dim3(Sn / 128, OD / 128, Bn), 256, S11_SMEM>>>(
        wv16, x16, bv, nullptr, v16,
        Cin, Cin, Sn, Cin / 32, 0, sxT, sv, 1.0f);

    // E = exp(q16 @ k16^T / sqrt(KD)) -> fp16 + psum   [m=s, n=t, k=kd]
    gemm_s<3><<<dim3(Sn / 128, Sn / 128, Bn), 256, S11_SMEM>>>(
        qk16, qk16 + KD, nullptr, psum, eP,
        QKN, QKN, Sn, KD / 32, sqk, sqk, ssc, 0.04419417382415922f);

    // inv rowsums
    reduce_inv<<<Bn * Sn / 256, 256>>>(psum, inv);

    // out = (v16 @ E^T) * inv[s] -> (B,OD,S) fp32 into d_out   [m=o, n=s, k=t]
    gemm_s<4><<<dim3(Sn / 128, OD / 128, Bn), 256, S11_SMEM>>>(
        v16, eP, nullptr, inv, out,
        Sn, Sn, Sn, Sn / 32, sv, ssc, sv, 1.0f);
}

// round 15
// speedup vs baseline: 1.5138x; 1.5138x over previous
#include <cuda_runtime.h>
#include <cuda_fp16.h>
#include <cstdint>
#include <math.h>

#define Bn  8
#define Cin 1024
#define Sn  2048
#define KD  512
#define OD  1024
#define QKN 1024   // merged q|k output width

// ---------------- scratch (all single fp16 planes) ---------------------------
__device__ __align__(128) __half g_x16 [(size_t)Bn * Sn * Cin];  // xT fp16 (B,S,C)
__device__ __align__(128) __half g_wqk [(size_t)QKN * Cin];      // [Wq|Wk] fp16
__device__ __align__(128) __half g_wv  [(size_t)OD * Cin];       // Wv fp16
__device__ __align__(128) float  g_bqk[QKN];
__device__ __align__(128) __half g_qk [(size_t)Bn * Sn * QKN];   // q cols 0-511, k 512-1023
__device__ __align__(128) __half g_v  [(size_t)Bn * OD * Sn];    // v fp16 (B,OD,S)
__device__ __align__(128) __half g_e  [(size_t)Bn * Sn * Sn];    // exp(scores) fp16
__device__ __align__(128) float  g_psum[(size_t)Bn * 16 * Sn];
__device__ __align__(128) float  g_inv[(size_t)Bn * Sn];

// ---------------- helpers ----------------------------------------------------
__device__ __forceinline__ uint32_t smem_u32(const void* p) {
    uint32_t a;
    asm("{ .reg .u64 t; cvta.to.shared.u64 t, %1; cvt.u32.u64 %0, t; }" : "=r"(a) : "l"(p));
    return a;
}

#define LDSM_X4(r0, r1, r2, r3, addr) \
    asm volatile("ldmatrix.sync.aligned.m8n8.x4.shared.b16 {%0,%1,%2,%3}, [%4];" \
                 : "=r"(r0), "=r"(r1), "=r"(r2), "=r"(r3) : "r"(addr))

__device__ __forceinline__ void mma16816h(float* d, const uint32_t* a, const uint32_t* b) {
    asm volatile(
        "mma.sync.aligned.m16n8k16.row.col.f32.f16.f16.f32 "
        "{%0,%1,%2,%3}, {%4,%5,%6,%7}, {%8,%9}, {%0,%1,%2,%3};"
        : "+f"(d[0]), "+f"(d[1]), "+f"(d[2]), "+f"(d[3])
        : "r"(a[0]), "r"(a[1]), "r"(a[2]), "r"(a[3]), "r"(b[0]), "r"(b[1]));
}

#define CP_ASYNC16(dst, src) \
    asm volatile("cp.async.cg.shared.global [%0], [%1], 16;" :: "r"(dst), "l"(src) : "memory")
#define CP_COMMIT()  asm volatile("cp.async.commit_group;" ::: "memory")
#define CP_WAIT(n)   asm volatile("cp.async.wait_group %0;" :: "n"(n) : "memory")

// tile: 128 rows x 32 fp16 (64B rows); 16B-chunk swizzle c4 ^= (row>>1)&3
__device__ __forceinline__ void cp_tile(uint32_t sdst, const __half* __restrict__ g,
                                        int ld, int row0, int kc, int tid) {
#pragma unroll
    for (int it = 0; it < 2; it++) {
        int slot = tid + it * 256;
        int row  = slot >> 2;
        int c4   = slot & 3;
        uint32_t off = (uint32_t)row * 64 + (uint32_t)((c4 ^ ((row >> 1) & 3)) << 4);
        CP_ASYNC16(sdst + off, g + (size_t)(row0 + row) * ld + kc * 32 + c4 * 8);
    }
}

#define NSTAGE 3

// ======= 1x1-plane fp16 GEMM, 128x128 tile, 1 CTA/SM (projections) ==========
// EPI: 1 = +bias[n], fp16 out (qk proj)   2 = +bias[m], fp16 out (v proj)
#define P_STAGE 16384        // A 8K | B 8K
#define P_SMEM  (NSTAGE * P_STAGE)

template<int EPI>
__global__ void __launch_bounds__(256)
gemm_p(const __half* __restrict__ A, const __half* __restrict__ B,
       const float* __restrict__ bias, __half* __restrict__ C,
       int lda, int ldb, int ldc, int nK,
       size_t sA, size_t sB, size_t sC)
{
    extern __shared__ __align__(1024) char smem[];
    const uint32_t sm = smem_u32(smem);
    const int tid  = threadIdx.x;
    const int lane = tid & 31;
    const int wid  = tid >> 5;
    const int m0   = blockIdx.y * 128;
    const int n0   = blockIdx.x * 128;
    const int mW   = (wid >> 2) * 64;
    const int nW   = (wid & 3) * 32;

    A += (size_t)blockIdx.z * sA;
    B += (size_t)blockIdx.z * sB;

    float acc[4][4][4];
#pragma unroll
    for (int i = 0; i < 4; i++)
#pragma unroll
        for (int j = 0; j < 4; j++) {
            acc[i][j][0] = 0.f; acc[i][j][1] = 0.f; acc[i][j][2] = 0.f; acc[i][j][3] = 0.f;
        }

    const uint32_t rl   = lane & 15;
    const uint32_t khA  = lane >> 4;
    const uint32_t swA  = (rl >> 1) & 3;
    const uint32_t aRow = (uint32_t)(mW + rl) * 64;
    const uint32_t rnl  = ((lane >> 4) << 3) | (lane & 7);
    const uint32_t khB  = (lane >> 3) & 1;
    const uint32_t swB  = (rnl >> 1) & 3;
    const uint32_t bRow = (uint32_t)(nW + rnl) * 64;

#pragma unroll
    for (int p = 0; p < 2; p++) {
        if (p < nK) {
            const uint32_t st = sm + p * P_STAGE;
            cp_tile(st,        A, lda, m0, p, tid);
            cp_tile(st + 8192, B, ldb, n0, p, tid);
        }
        CP_COMMIT();
    }

    for (int i = 0; i < nK; i++) {
        CP_WAIT(1);
        __syncthreads();

        const uint32_t stg = sm + (uint32_t)(i % NSTAGE) * P_STAGE;
#pragma unroll
        for (int ks = 0; ks < 2; ks++) {
            const uint32_t aCh = (uint32_t)((ks * 2 + khA) ^ swA) << 4;
            const uint32_t bCh = (uint32_t)((ks * 2 + khB) ^ swB) << 4;
            uint32_t a[4][4], b[8];
#pragma unroll
            for (int mt = 0; mt < 4; mt++) {
                LDSM_X4(a[mt][0], a[mt][1], a[mt][2], a[mt][3],
                        stg + aRow + mt * 1024 + aCh);
            }
            LDSM_X4(b[0], b[1], b[2], b[3], stg + 8192 + bRow + bCh);
            LDSM_X4(b[4], b[5], b[6], b[7], stg + 8192 + bRow + 1024 + bCh);

#pragma unroll
            for (int mt = 0; mt < 4; mt++)
#pragma unroll
                for (int nt = 0; nt < 4; nt++)
                    mma16816h(acc[mt][nt], a[mt], &b[nt * 2]);
        }

        const int nx = i + 2;
        if (nx < nK) {
            const uint32_t st = sm + (uint32_t)(nx % NSTAGE) * P_STAGE;
            cp_tile(st,        A, lda, m0, nx, tid);
            cp_tile(st + 8192, B, ldb, n0, nx, tid);
        }
        CP_COMMIT();
    }

    // ---- epilogue ----
    const int g  = lane >> 2;
    const int tg = lane & 3;
#pragma unroll
    for (int mt = 0; mt < 4; mt++) {
        const int m = m0 + mW + mt * 16 + g;
        float bm0 = 0.f, bm8 = 0.f;
        if (EPI == 2) { bm0 = bias[m]; bm8 = bias[m + 8]; }
#pragma unroll
        for (int nt = 0; nt < 4; nt++) {
            const int n = n0 + nW + nt * 8 + tg * 2;
            float d0 = acc[mt][nt][0];
            float d1 = acc[mt][nt][1];
            float d2 = acc[mt][nt][2];
            float d3 = acc[mt][nt][3];
            if (EPI == 1) {
                float2 bb = *(const float2*)(bias + n);
                d0 += bb.x; d1 += bb.y; d2 += bb.x; d3 += bb.y;
            } else {
                d0 += bm0; d1 += bm0; d2 += bm8; d3 += bm8;
            }
            __half* Ch = C + (size_t)blockIdx.z * sC;
            *(__half2*)(Ch + (size_t)m * ldc + n) =
                __halves2half2(__float2half(d0), __float2half(d1));
            *(__half2*)(Ch + (size_t)(m + 8) * ldc + n) =
                __halves2half2(__float2half(d2), __float2half(d3));
        }
    }
}

// ======= 1x1-plane fp16 GEMM, 128x128 tile, 2 CTAs/SM (scores / PV) =========
// EPI: 3 = exp(d*alpha) -> fp16 out + renormalized psum
//      4 = d * inv[b*Sn+n], fp32 out
template<int EPI>
__global__ void __launch_bounds__(256, 2)
gemm_s(const __half* __restrict__ A, const __half* __restrict__ B,
       float* __restrict__ aux, void* __restrict__ C,
       int lda, int ldb, int ldc, int nK,
       size_t sA, size_t sB, size_t sC, float alpha)
{
    extern __shared__ __align__(1024) char smem[];
    const uint32_t sm = smem_u32(smem);
    const int tid  = threadIdx.x;
    const int lane = tid & 31;
    const int wid  = tid >> 5;
    const int m0   = blockIdx.y * 128;
    const int n0   = blockIdx.x * 128;
    const int mW   = (wid >> 2) * 64;
    const int nW   = (wid & 3) * 32;

    A += (size_t)blockIdx.z * sA;
    B += (size_t)blockIdx.z * sB;

    float acc[4][4][4];
#pragma unroll
    for (int i = 0; i < 4; i++)
#pragma unroll
        for (int j = 0; j < 4; j++) {
            acc[i][j][0] = 0.f; acc[i][j][1] = 0.f; acc[i][j][2] = 0.f; acc[i][j][3] = 0.f;
        }

    const uint32_t rl   = lane & 15;
    const uint32_t khA  = lane >> 4;
    const uint32_t swA  = (rl >> 1) & 3;
    const uint32_t aRow = (uint32_t)(mW + rl) * 64;
    const uint32_t rnl  = ((lane >> 4) << 3) | (lane & 7);
    const uint32_t khB  = (lane >> 3) & 1;
    const uint32_t swB  = (rnl >> 1) & 3;
    const uint32_t bRow = (uint32_t)(nW + rnl) * 64;

#pragma unroll
    for (int p = 0; p < 2; p++) {
        if (p < nK) {
            const uint32_t st = sm + p * P_STAGE;
            cp_tile(st,        A, lda, m0, p, tid);
            cp_tile(st + 8192, B, ldb, n0, p, tid);
        }
        CP_COMMIT();
    }

    for (int i = 0; i < nK; i++) {
        CP_WAIT(1);
        __syncthreads();

        const uint32_t stg = sm + (uint32_t)(i % NSTAGE) * P_STAGE;
#pragma unroll
        for (int ks = 0; ks < 2; ks++) {
            const uint32_t aCh = (uint32_t)((ks * 2 + khA) ^ swA) << 4;
            const uint32_t bCh = (uint32_t)((ks * 2 + khB) ^ swB) << 4;
            uint32_t a[4][4], b[8];
#pragma unroll
            for (int mt = 0; mt < 4; mt++) {
                LDSM_X4(a[mt][0], a[mt][1], a[mt][2], a[mt][3],
                        stg + aRow + mt * 1024 + aCh);
            }
            LDSM_X4(b[0], b[1], b[2], b[3], stg + 8192 + bRow + bCh);
            LDSM_X4(b[4], b[5], b[6], b[7], stg + 8192 + bRow + 1024 + bCh);

#pragma unroll
            for (int mt = 0; mt < 4; mt++)
#pragma unroll
                for (int nt = 0; nt < 4; nt++)
                    mma16816h(acc[mt][nt], a[mt], &b[nt * 2]);
        }

        const int nx = i + 2;
        if (nx < nK) {
            const uint32_t st = sm + (uint32_t)(nx % NSTAGE) * P_STAGE;
            cp_tile(st,        A, lda, m0, nx, tid);
            cp_tile(st + 8192, B, ldb, n0, nx, tid);
        }
        CP_COMMIT();
    }
    __syncthreads();   // smem reusable below

    // ---- epilogue ----
    const int g  = lane >> 2;
    const int tg = lane & 3;
    float rsum[4][2];
    if (EPI == 3) {
#pragma unroll
        for (int mt = 0; mt < 4; mt++) { rsum[mt][0] = 0.f; rsum[mt][1] = 0.f; }
    }

#pragma unroll
    for (int mt = 0; mt < 4; mt++) {
        const int m = m0 + mW + mt * 16 + g;
#pragma unroll
        for (int nt = 0; nt < 4; nt++) {
            const int n = n0 + nW + nt * 8 + tg * 2;
            float d0 = acc[mt][nt][0] * alpha;
            float d1 = acc[mt][nt][1] * alpha;
            float d2 = acc[mt][nt][2] * alpha;
            float d3 = acc[mt][nt][3] * alpha;
            if (EPI == 3) {
                __half e0 = __float2half(__expf(d0));
                __half e1 = __float2half(__expf(d1));
                __half e2 = __float2half(__expf(d2));
                __half e3 = __float2half(__expf(d3));
                // accumulate ROUNDED values -> normalization exact
                rsum[mt][0] += __half2float(e0) + __half2float(e1);
                rsum[mt][1] += __half2float(e2) + __half2float(e3);
                __half* Ch = (__half*)C + (size_t)blockIdx.z * sC;
                *(__half2*)(Ch + (size_t)m * ldc + n)       = __halves2half2(e0, e1);
                *(__half2*)(Ch + (size_t)(m + 8) * ldc + n) = __halves2half2(e2, e3);
            } else {
                float2 iv = *(const float2*)(aux + (size_t)blockIdx.z * Sn + n);
                float* Cf = (float*)C + (size_t)blockIdx.z * sC;
                float2 o0 = { d0 * iv.x, d1 * iv.y };
                float2 o1 = { d2 * iv.x, d3 * iv.y };
                *(float2*)(Cf + (size_t)m * ldc + n)       = o0;
                *(float2*)(Cf + (size_t)(m + 8) * ldc + n) = o1;
            }
        }
    }

    if (EPI == 3) {
#pragma unroll
        for (int mt = 0; mt < 4; mt++) {
#pragma unroll
            for (int h = 0; h < 2; h++) {
                float s = rsum[mt][h];
                s += __shfl_xor_sync(0xffffffffu, s, 1);
                s += __shfl_xor_sync(0xffffffffu, s, 2);
                rsum[mt][h] = s;
            }
        }
        float* ss = (float*)smem;
        const int nWj = wid & 3;
        if (tg == 0) {
#pragma unroll
            for (int mt = 0; mt < 4; mt++) {
                ss[nWj * 128 + mW + mt * 16 + g]     = rsum[mt][0];
                ss[nWj * 128 + mW + mt * 16 + 8 + g] = rsum[mt][1];
            }
        }
        __syncthreads();
        if (tid < 128) {
            float t = ss[tid] + ss[128 + tid] + ss[256 + tid] + ss[384 + tid];
            aux[((size_t)blockIdx.z * 16 + blockIdx.x) * Sn + m0 + tid] = t;
        }
    }
}

// ---------------- converters --------------------------------------------------
__global__ void __launch_bounds__(256)
xpose16(const float* __restrict__ x, __half* __restrict__ xT)
{
    __shared__ float t[32][33];
    const int tx = threadIdx.x, ty = threadIdx.y;
    const int s0 = blockIdx.x * 32, c0 = blockIdx.y * 32;
    const size_t bi = (size_t)blockIdx.z * Cin * Sn;
    const size_t bo = (size_t)blockIdx.z * Sn * Cin;
#pragma unroll
    for (int j = ty; j < 32; j += 8)
        t[j][tx] = x[bi + (size_t)(c0 + j) * Sn + s0 + tx];
    __syncthreads();
#pragma unroll
    for (int j = ty; j < 32; j += 8)
        xT[bo + (size_t)(s0 + j) * Cin + c0 + tx] = __float2half(t[tx][j]);
}

__global__ void __launch_bounds__(256)
cvt16(const float* __restrict__ in, __half* __restrict__ o, int n4)
{
    int i = blockIdx.x * 256 + threadIdx.x;
    if (i < n4) {
        float4 v = ((const float4*)in)[i];
        ((__half2*)o)[i * 2]     = __halves2half2(__float2half(v.x), __float2half(v.y));
        ((__half2*)o)[i * 2 + 1] = __halves2half2(__float2half(v.z), __float2half(v.w));
    }
}

__global__ void __launch_bounds__(256)
reduce_inv(const float* __restrict__ psum, float* __restrict__ inv)
{
    int i = blockIdx.x * 256 + threadIdx.x;
    int b = i >> 11, s = i & 2047;
    const float* p = psum + (size_t)b * 16 * Sn + s;
    float t = 0.f;
#pragma unroll
    for (int j = 0; j < 16; j++) t += p[(size_t)j * Sn];
    inv[i] = 1.0f / t;
}

// -----------------------------------------------------------------------------
extern "C" void kernel_launch(void* const* d_in, const int* in_sizes, int n_in,
                              void* d_out, int out_size)
{
    (void)in_sizes; (void)n_in; (void)out_size;
    const float* x  = (const float*)d_in[0];
    const float* wq = (const float*)d_in[1];
    const float* bq = (const float*)d_in[2];
    const float* wk = (const float*)d_in[3];
    const float* bk = (const float*)d_in[4];
    const float* wv = (const float*)d_in[5];
    const float* bv = (const float*)d_in[6];
    float* out = (float*)d_out;

    __half *x16, *wqk, *wv16, *qk16, *v16, *eP;
    float *bqk, *psum, *inv;
    cudaGetSymbolAddress((void**)&x16,  g_x16);
    cudaGetSymbolAddress((void**)&wqk,  g_wqk);
    cudaGetSymbolAddress((void**)&wv16, g_wv);
    cudaGetSymbolAddress((void**)&bqk,  g_bqk);
    cudaGetSymbolAddress((void**)&qk16, g_qk);
    cudaGetSymbolAddress((void**)&v16,  g_v);
    cudaGetSymbolAddress((void**)&eP,   g_e);
    cudaGetSymbolAddress((void**)&psum, g_psum);  cudaGetSymbolAddress((void**)&inv,  g_inv);

    cudaFuncSetAttribute(gemm_p<1>, cudaFuncAttributeMaxDynamicSharedMemorySize, P_SMEM);
    cudaFuncSetAttribute(gemm_p<2>, cudaFuncAttributeMaxDynamicSharedMemorySize, P_SMEM);
    cudaFuncSetAttribute(gemm_s<3>, cudaFuncAttributeMaxDynamicSharedMemorySize, P_SMEM);
    cudaFuncSetAttribute(gemm_s<4>, cudaFuncAttributeMaxDynamicSharedMemorySize, P_SMEM);

    // ---- conversions ----
    xpose16<<<dim3(Sn / 32, Cin / 32, Bn), dim3(32, 8)>>>(x, x16);
    cvt16<<<(KD * Cin / 4 + 255) / 256, 256>>>(wq, wqk, KD * Cin / 4);
    cvt16<<<(KD * Cin / 4 + 255) / 256, 256>>>(wk, wqk + (size_t)KD * Cin, KD * Cin / 4);
    cvt16<<<(OD * Cin / 4 + 255) / 256, 256>>>(wv, wv16, OD * Cin / 4);
    cudaMemcpyAsync(bqk,      bq, KD * sizeof(float), cudaMemcpyDeviceToDevice, 0);
    cudaMemcpyAsync(bqk + KD, bk, KD * sizeof(float), cudaMemcpyDeviceToDevice, 0);

    const size_t sxT = (size_t)Sn * Cin;
    const size_t sqk = (size_t)Sn * QKN;
    const size_t sv  = (size_t)OD * Sn;
    const size_t ssc = (size_t)Sn * Sn;

    // qk = x16 @ Wqk^T + bias -> (B,S,1024) fp16   [m=s, n=ch, k=c]
    gemm_p<1><<<dim3(QKN / 128, Sn / 128, Bn), 256, P_SMEM>>>(
        x16, wqk, bqk, qk16,
        Cin, Cin, QKN, Cin / 32, sxT, 0, sqk);

    // v = Wv @ x16 + bv -> (B,OD,S) fp16   [m=o, n=s, k=c]
    gemm_p<2><<<dim3(Sn / 128, OD / 128, Bn), 256, P_SMEM>>>(
        wv16, x16, bv, v16,
        Cin, Cin, Sn, Cin / 32, 0, sxT, sv);

    // E = exp(q16 @ k16^T / sqrt(KD)) -> fp16 + psum   [m=s, n=t, k=kd]
    gemm_s<3><<<dim3(Sn / 128, Sn / 128, Bn), 256, P_SMEM>>>(
        qk16, qk16 + KD, psum, eP,
        QKN, QKN, Sn, KD / 32, sqk, sqk, ssc, 0.04419417382415922f);

    // inv rowsums
    reduce_inv<<<Bn * Sn / 256, 256>>>(psum, inv);

    // out = (v16 @ E^T) * inv[s] -> (B,OD,S) fp32 into d_out   [m=o, n=s, k=t]
    gemm_s<4><<<dim3(Sn / 128, OD / 128, Bn), 256, P_SMEM>>>(
        v16, eP, inv, out,
        Sn, Sn, Sn, Sn / 32, sv, ssc, sv, 1.0f);
}

// round 16
// speedup vs baseline: 1.5576x; 1.0290x over previous
#include <cuda_runtime.h>
#include <cuda_fp16.h>
#include <cstdint>
#include <math.h>

#define Bn  8
#define Cin 1024
#define Sn  2048
#define KD  512
#define OD  1024
#define QKN 1024   // merged q|k output width

// ---------------- scratch (all single fp16 planes) ---------------------------
__device__ __align__(128) __half g_x16 [(size_t)Bn * Sn * Cin];  // xT fp16 (B,S,C)
__device__ __align__(128) __half g_wqk [(size_t)QKN * Cin];      // [Wq|Wk] fp16
__device__ __align__(128) __half g_wv  [(size_t)OD * Cin];       // Wv fp16
__device__ __align__(128) float  g_bqk[QKN];
__device__ __align__(128) __half g_qk [(size_t)Bn * Sn * QKN];   // q (pre-scaled) 0-511, k 512-1023
__device__ __align__(128) __half g_v  [(size_t)Bn * OD * Sn];    // v fp16 (B,OD,S)
__device__ __align__(128) __half g_e  [(size_t)Bn * Sn * Sn];    // exp(scores) fp16
__device__ __align__(128) float  g_psum[(size_t)Bn * 16 * Sn];
__device__ __align__(128) float  g_inv[(size_t)Bn * Sn];

// ---------------- helpers ----------------------------------------------------
__device__ __forceinline__ uint32_t smem_u32(const void* p) {
    uint32_t a;
    asm("{ .reg .u64 t; cvta.to.shared.u64 t, %1; cvt.u32.u64 %0, t; }" : "=r"(a) : "l"(p));
    return a;
}

#define LDSM_X4(r0, r1, r2, r3, addr) \
    asm volatile("ldmatrix.sync.aligned.m8n8.x4.shared.b16 {%0,%1,%2,%3}, [%4];" \
                 : "=r"(r0), "=r"(r1), "=r"(r2), "=r"(r3) : "r"(addr))

__device__ __forceinline__ void mma16816h(float* d, const uint32_t* a, const uint32_t* b) {
    asm volatile(
        "mma.sync.aligned.m16n8k16.row.col.f32.f16.f16.f32 "
        "{%0,%1,%2,%3}, {%4,%5,%6,%7}, {%8,%9}, {%0,%1,%2,%3};"
        : "+f"(d[0]), "+f"(d[1]), "+f"(d[2]), "+f"(d[3])
        : "r"(a[0]), "r"(a[1]), "r"(a[2]), "r"(a[3]), "r"(b[0]), "r"(b[1]));
}

#define CP_ASYNC16(dst, src) \
    asm volatile("cp.async.cg.shared.global [%0], [%1], 16;" :: "r"(dst), "l"(src) : "memory")
#define CP_COMMIT()  asm volatile("cp.async.commit_group;" ::: "memory")
#define CP_WAIT(n)   asm volatile("cp.async.wait_group %0;" :: "n"(n) : "memory")

// BK=64 tile: 128 rows x 64 fp16 (128B rows); SW128 swizzle: 16B-chunk c ^= row&7
__device__ __forceinline__ void cp_tile64(uint32_t sdst, const __half* __restrict__ g,
                                          int ld, int row0, int kc, int tid) {
#pragma unroll
    for (int it = 0; it < 4; it++) {
        int slot = tid + it * 256;                 // 0..1023
        int row  = slot >> 3;                      // 0..127
        int c    = slot & 7;                       // 16B chunk
        uint32_t off = (uint32_t)row * 128 + (uint32_t)((c ^ (row & 7)) << 4);
        CP_ASYNC16(sdst + off, g + (size_t)(row0 + row) * ld + kc * 64 + c * 8);
    }
}

#define NSTAGE  3
#define STG     32768          // A 16K | B 16K
#define SM_TOT  (NSTAGE * STG)

// ================= 1x1-plane fp16 GEMM, 128x128 tile, BK=64 =================
// D[m,n] = alpha * sum_k A[m,k]*B[n,k]
// EPI: 1 = (+bias[n]); q-half (n<KD) additionally scaled by qs; fp16 out
//      2 = +bias[m], fp16 out             (v projection)
//      3 = exp(d) -> fp16 out + renormalized psum (scores; alpha pre-folded)
//      4 = d * inv[b*Sn+n], fp32 out      (PV, deferred normalization)
template<int EPI>
__global__ void __launch_bounds__(256)
gemm_g(const __half* __restrict__ A, const __half* __restrict__ B,
       const float* __restrict__ bias, float* __restrict__ aux,
       void* __restrict__ C,
       int lda, int ldb, int ldc, int nK,
       size_t sA, size_t sB, size_t sC, float qs)
{
    extern __shared__ __align__(1024) char smem[];
    const uint32_t sm = smem_u32(smem);
    const int tid  = threadIdx.x;
    const int lane = tid & 31;
    const int wid  = tid >> 5;
    const int m0   = blockIdx.y * 128;
    const int n0   = blockIdx.x * 128;
    const int mW   = (wid >> 2) * 64;
    const int nW   = (wid & 3) * 32;

    A += (size_t)blockIdx.z * sA;
    B += (size_t)blockIdx.z * sB;

    float acc[4][4][4];
#pragma unroll
    for (int i = 0; i < 4; i++)
#pragma unroll
        for (int j = 0; j < 4; j++) {
            acc[i][j][0] = 0.f; acc[i][j][1] = 0.f; acc[i][j][2] = 0.f; acc[i][j][3] = 0.f;
        }

    // fragment addressing: 128B rows, full SW128 swizzle on 16B-chunk index
    const uint32_t rl   = lane & 15;
    const uint32_t khA  = lane >> 4;
    const uint32_t swA  = rl & 7;
    const uint32_t aRow = (uint32_t)(mW + rl) * 128;
    const uint32_t rnl  = ((lane >> 4) << 3) | (lane & 7);
    const uint32_t khB  = (lane >> 3) & 1;
    const uint32_t swB  = rnl & 7;
    const uint32_t bRow = (uint32_t)(nW + rnl) * 128;

#pragma unroll
    for (int p = 0; p < 2; p++) {
        if (p < nK) {
            const uint32_t st = sm + p * STG;
            cp_tile64(st,         A, lda, m0, p, tid);
            cp_tile64(st + 16384, B, ldb, n0, p, tid);
        }
        CP_COMMIT();
    }

    for (int i = 0; i < nK; i++) {
        CP_WAIT(1);
        __syncthreads();

        const uint32_t stg = sm + (uint32_t)(i % NSTAGE) * STG;
#pragma unroll
        for (int ks = 0; ks < 4; ks++) {
            const uint32_t aCh = (uint32_t)(((uint32_t)(ks * 2) + khA) ^ swA) << 4;
            const uint32_t bCh = (uint32_t)(((uint32_t)(ks * 2) + khB) ^ swB) << 4;
            uint32_t a[4][4], b[8];
#pragma unroll
            for (int mt = 0; mt < 4; mt++) {
                LDSM_X4(a[mt][0], a[mt][1], a[mt][2], a[mt][3],
                        stg + aRow + mt * 2048 + aCh);
            }
            LDSM_X4(b[0], b[1], b[2], b[3], stg + 16384 + bRow + bCh);
            LDSM_X4(b[4], b[5], b[6], b[7], stg + 16384 + bRow + 2048 + bCh);

#pragma unroll
            for (int mt = 0; mt < 4; mt++)
#pragma unroll
                for (int nt = 0; nt < 4; nt++)
                    mma16816h(acc[mt][nt], a[mt], &b[nt * 2]);
        }

        const int nx = i + 2;
        if (nx < nK) {
            const uint32_t st = sm + (uint32_t)(nx % NSTAGE) * STG;
            cp_tile64(st,         A, lda, m0, nx, tid);
            cp_tile64(st + 16384, B, ldb, n0, nx, tid);
        }
        CP_COMMIT();
    }
    __syncthreads();   // smem reusable below

    // ---- epilogue ----
    const int g  = lane >> 2;
    const int tg = lane & 3;
    float rsum[4][2];
    if (EPI == 3) {
#pragma unroll
        for (int mt = 0; mt < 4; mt++) { rsum[mt][0] = 0.f; rsum[mt][1] = 0.f; }
    }

#pragma unroll
    for (int mt = 0; mt < 4; mt++) {
        const int m = m0 + mW + mt * 16 + g;
        float bm0 = 0.f, bm8 = 0.f;
        if (EPI == 2) { bm0 = bias[m]; bm8 = bias[m + 8]; }
#pragma unroll
        for (int nt = 0; nt < 4; nt++) {
            const int n = n0 + nW + nt * 8 + tg * 2;
            float d0 = acc[mt][nt][0];
            float d1 = acc[mt][nt][1];
            float d2 = acc[mt][nt][2];
            float d3 = acc[mt][nt][3];
            if (EPI == 1) {
                float2 bb = *(const float2*)(bias + n);
                d0 += bb.x; d1 += bb.y; d2 += bb.x; d3 += bb.y;
                if (n0 < KD) {                    // q half: fold 1/sqrt(KD)
                    d0 *= qs; d1 *= qs; d2 *= qs; d3 *= qs;
                }
            } else if (EPI == 2) {
                d0 += bm0; d1 += bm0; d2 += bm8; d3 += bm8;
            }
            if (EPI == 4) {
                float2 iv = *(const float2*)(aux + (size_t)blockIdx.z * Sn + n);
                float* Cf = (float*)C + (size_t)blockIdx.z * sC;
                float2 o0 = { d0 * iv.x, d1 * iv.y };
                float2 o1 = { d2 * iv.x, d3 * iv.y };
                *(float2*)(Cf + (size_t)m * ldc + n)       = o0;
                *(float2*)(Cf + (size_t)(m + 8) * ldc + n) = o1;
            } else {
                __half e0, e1, e2, e3;
                if (EPI == 3) {
                    e0 = __float2half(__expf(d0));
                    e1 = __float2half(__expf(d1));
                    e2 = __float2half(__expf(d2));
                    e3 = __float2half(__expf(d3));
                    // accumulate ROUNDED values -> normalization exact
                    rsum[mt][0] += __half2float(e0) + __half2float(e1);
                    rsum[mt][1] += __half2float(e2) + __half2float(e3);
                } else {
                    e0 = __float2half(d0); e1 = __float2half(d1);
                    e2 = __float2half(d2); e3 = __float2half(d3);
                }
                __half* Ch = (__half*)C + (size_t)blockIdx.z * sC;
                *(__half2*)(Ch + (size_t)m * ldc + n)       = __halves2half2(e0, e1);
                *(__half2*)(Ch + (size_t)(m + 8) * ldc + n) = __halves2half2(e2, e3);
            }
        }
    }

    if (EPI == 3) {
#pragma unroll
        for (int mt = 0; mt < 4; mt++) {
#pragma unroll
            for (int h = 0; h < 2; h++) {
                float s = rsum[mt][h];
                s += __shfl_xor_sync(0xffffffffu, s, 1);
                s += __shfl_xor_sync(0xffffffffu, s, 2);
                rsum[mt][h] = s;
            }
        }
        float* ss = (float*)smem;
        const int nWj = wid & 3;
        if (tg == 0) {
#pragma unroll
            for (int mt = 0; mt < 4; mt++) {
                ss[nWj * 128 + mW + mt * 16 + g]     = rsum[mt][0];
                ss[nWj * 128 + mW + mt * 16 + 8 + g] = rsum[mt][1];
            }
        }
        __syncthreads();
        if (tid < 128) {
            float t = ss[tid] + ss[128 + tid] + ss[256 + tid] + ss[384 + tid];
            aux[((size_t)blockIdx.z * 16 + blockIdx.x) * Sn + m0 + tid] = t;
        }
    }
}

// ---------------- converters --------------------------------------------------
__global__ void __launch_bounds__(256)
xpose16(const float* __restrict__ x, __half* __restrict__ xT)
{
    __shared__ float t[32][33];
    const int tx = threadIdx.x, ty = threadIdx.y;
    const int s0 = blockIdx.x * 32, c0 = blockIdx.y * 32;
    const size_t bi = (size_t)blockIdx.z * Cin * Sn;
    const size_t bo = (size_t)blockIdx.z * Sn * Cin;
#pragma unroll
    for (int j = ty; j < 32; j += 8)
        t[j][tx] = x[bi + (size_t)(c0 + j) * Sn + s0 + tx];
    __syncthreads();
#pragma unroll
    for (int j = ty; j < 32; j += 8)
        xT[bo + (size_t)(s0 + j) * Cin + c0 + tx] = __float2half(t[tx][j]);
}

__global__ void __launch_bounds__(256)
cvt16(const float* __restrict__ in, __half* __restrict__ o, int n4)
{
    int i = blockIdx.x * 256 + threadIdx.x;
    if (i < n4) {
        float4 v = ((const float4*)in)[i];
        ((__half2*)o)[i * 2]     = __halves2half2(__float2half(v.x), __float2half(v.y));
        ((__half2*)o)[i * 2 + 1] = __halves2half2(__float2half(v.z), __float2half(v.w));
    }
}

__global__ void __launch_bounds__(256)
reduce_inv(const float* __restrict__ psum, float* __restrict__ inv)
{
    int i = blockIdx.x * 256 + threadIdx.x;
    int b = i >> 11, s = i & 2047;
    const float* p = psum + (size_t)b * 16 * Sn + s;
    float t = 0.f;
#pragma unroll
    for (int j = 0; j < 16; j++) t += p[(size_t)j * Sn];
    inv[i] = 1.0f / t;
}

// -----------------------------------------------------------------------------
extern "C" void kernel_launch(void* const* d_in, const int* in_sizes, int n_in,
                              void* d_out, int out_size)
{
    (void)in_sizes; (void)n_in; (void)out_size;
    const float* x  = (const float*)d_in[0];
    const float* wq = (const float*)d_in[1];
    const float* bq = (const float*)d_in[2];
    const float* wk = (const float*)d_in[3];
    const float* bk = (const float*)d_in[4];
    const float* wv = (const float*)d_in[5];
    const float* bv = (const float*)d_in[6];
    float* out = (float*)d_out;

    __half *x16, *wqk, *wv16, *qk16, *v16, *eP;
    float *bqk, *psum, *inv;
    cudaGetSymbolAddress((void**)&x16,  g_x16);
    cudaGetSymbolAddress((void**)&wqk,  g_wqk);
    cudaGetSymbolAddress((void**)&wv16, g_wv);
    cudaGetSymbolAddress((void**)&bqk,  g_bqk);
    cudaGetSymbolAddress((void**)&qk16, g_qk);
    cudaGetSymbolAddress((void**)&v16,  g_v);
    cudaGetSymbolAddress((void**)&eP,   g_e);
    cudaGetSymbolAddress((void**)&psum, g_psum);  cudaGetSymbolAddress((void**)&inv,  g_inv);

    cudaFuncSetAttribute(gemm_g<1>, cudaFuncAttributeMaxDynamicSharedMemorySize, SM_TOT);
    cudaFuncSetAttribute(gemm_g<2>, cudaFuncAttributeMaxDynamicSharedMemorySize, SM_TOT);
    cudaFuncSetAttribute(gemm_g<3>, cudaFuncAttributeMaxDynamicSharedMemorySize, SM_TOT);
    cudaFuncSetAttribute(gemm_g<4>, cudaFuncAttributeMaxDynamicSharedMemorySize, SM_TOT);

    // ---- conversions ----
    xpose16<<<dim3(Sn / 32, Cin / 32, Bn), dim3(32, 8)>>>(x, x16);
    cvt16<<<(KD * Cin / 4 + 255) / 256, 256>>>(wq, wqk, KD * Cin / 4);
    cvt16<<<(KD * Cin / 4 + 255) / 256, 256>>>(wk, wqk + (size_t)KD * Cin, KD * Cin / 4);
    cvt16<<<(OD * Cin / 4 + 255) / 256, 256>>>(wv, wv16, OD * Cin / 4);
    cudaMemcpyAsync(bqk,      bq, KD * sizeof(float), cudaMemcpyDeviceToDevice, 0);
    cudaMemcpyAsync(bqk + KD, bk, KD * sizeof(float), cudaMemcpyDeviceToDevice, 0);

    const size_t sxT = (size_t)Sn * Cin;
    const size_t sqk = (size_t)Sn * QKN;
    const size_t sv  = (size_t)OD * Sn;
    const size_t ssc = (size_t)Sn * Sn;

    // qk = x16 @ Wqk^T + bias (q pre-scaled by 1/sqrt(KD)) -> (B,S,1024) fp16
    gemm_g<1><<<dim3(QKN / 128, Sn / 128, Bn), 256, SM_TOT>>>(
        x16, wqk, bqk, nullptr, qk16,
        Cin, Cin, QKN, Cin / 64, sxT, 0, sqk, 0.04419417382415922f);

    // v = Wv @ x16 + bv -> (B,OD,S) fp16   [m=o, n=s, k=c]
    gemm_g<2><<<dim3(Sn / 128, OD / 128, Bn), 256, SM_TOT>>>(
        wv16, x16, bv, nullptr, v16,
        Cin, Cin, Sn, Cin / 64, 0, sxT, sv, 1.0f);

    // E = exp(q16 @ k16^T) -> fp16 + psum   [m=s, n=t, k=kd]  (scale folded into q)
    gemm_g<3><<<dim3(Sn / 128, Sn / 128, Bn), 256, SM_TOT>>>(
        qk16, qk16 + KD, nullptr, psum, eP,
        QKN, QKN, Sn, KD / 64, sqk, sqk, ssc, 1.0f);

    // inv rowsums
    reduce_inv<<<Bn * Sn / 256, 256>>>(psum, inv);

    // out = (v16 @ E^T) * inv[s] -> (B,OD,S) fp32 into d_out   [m=o, n=s, k=t]
    gemm_g<4><<<dim3(Sn / 128, OD / 128, Bn), 256, SM_TOT>>>(
        v16, eP, nullptr, inv, out,
        Sn, Sn, Sn, Sn / 64, sv, ssc, sv, 1.0f);
}